// round 13
// baseline (speedup 1.0000x reference)
#include <cuda_runtime.h>

#define N_NODES 100000
#define N_EDGES 1600000
#define IN_DIM 64
#define HID_DIM 128
#define OUT_DIM 40
#define CAP 80
#define TILE 128
#define NTILES ((N_NODES + TILE - 1) / TILE)   // 782
#define ASTRIDE 132                 // [k][node] tile stride (128 + 4 pad)

// ---------------- scratch ----------------
__device__ __align__(16) float g_agg1[N_NODES * IN_DIM];
__device__ __align__(16) float g_t[N_NODES * OUT_DIM];
__device__ int g_deg[N_NODES];
__device__ int g_csr[N_NODES * CAP];
__device__ int g_is64;

typedef unsigned long long ull;
__device__ __forceinline__ ull f2pack(float lo, float hi) {
    ull r; asm("mov.b64 %0, {%1,%2};" : "=l"(r) : "f"(lo), "f"(hi)); return r;
}
__device__ __forceinline__ void f2unpack(ull v, float& lo, float& hi) {
    asm("mov.b64 {%0,%1}, %2;" : "=f"(lo), "=f"(hi) : "l"(v));
}
__device__ __forceinline__ ull fma2(ull a, ull b, ull c) {
    ull d; asm("fma.rn.f32x2 %0, %1, %2, %3;" : "=l"(d)
               : "l"(a), "l"(b), "l"(c)); return d;
}

// ---------------- K-prep ----------------
__global__ void k_prep(const long long* __restrict__ ei) {
    int i = blockIdx.x * blockDim.x + threadIdx.x;
    if (i < N_NODES) g_deg[i] = 0;
    if (blockIdx.x == 0) {
        long long v = ei[threadIdx.x];
        int ok = (v >= 0 && v < N_NODES);
        int all = __syncthreads_and(ok);
        if (threadIdx.x == 0) g_is64 = all;
    }
}

// ---------------- K-build ----------------
__global__ void k_build(const void* __restrict__ ei) {
    int e = blockIdx.x * blockDim.x + threadIdx.x;
    if (e >= N_EDGES) return;
    int s, d;
    if (g_is64) {
        s = (int)((const long long*)ei)[e];
        d = (int)((const long long*)ei)[N_EDGES + e];
    } else {
        s = ((const int*)ei)[e];
        d = ((const int*)ei)[N_EDGES + e];
    }
    int slot = atomicAdd(&g_deg[d], 1);
    if (slot < CAP) g_csr[d * CAP + slot] = s;
}

// ---------------- K-gather1 ----------------
__global__ void k_gather1(const float* __restrict__ x) {
    int w = (blockIdx.x * blockDim.x + threadIdx.x) >> 5;
    if (w >= N_NODES) return;
    int lane = threadIdx.x & 31;
    int p = lane >> 4;
    int c = lane & 15;
    int deg = min(g_deg[w], CAP);
    const int* row = g_csr + (size_t)w * CAP;

    float4 acc = make_float4(0.f, 0.f, 0.f, 0.f);
    if (p == 0)
        acc = *reinterpret_cast<const float4*>(x + (size_t)w * IN_DIM + c * 4);

    #pragma unroll 4
    for (int j = 0; j < deg; j += 2) {
        if (j + p < deg) {
            int s = row[j + p];
            float4 v = *reinterpret_cast<const float4*>(
                x + (size_t)s * IN_DIM + c * 4);
            acc.x += v.x; acc.y += v.y; acc.z += v.z; acc.w += v.w;
        }
    }
    acc.x += __shfl_xor_sync(0xffffffffu, acc.x, 16);
    acc.y += __shfl_xor_sync(0xffffffffu, acc.y, 16);
    acc.z += __shfl_xor_sync(0xffffffffu, acc.z, 16);
    acc.w += __shfl_xor_sync(0xffffffffu, acc.w, 16);
    if (p == 0)
        *reinterpret_cast<float4*>(g_agg1 + (size_t)w * IN_DIM + c * 4) = acc;
}

// ---------------- K2: fused MLP — cols-per-lane mapping ---------------------
// Warp = 8 fixed nodes (nb), lanes span all 128 cols (c = lane + 32j).
// Weight reads are warp-contiguous (1 wf); act reads warp-broadcast.
constexpr int S_W2 = 0;                          // [k][c] 128*128 = 16384
constexpr int S_W3 = S_W2 + HID_DIM * HID_DIM;   // [k][c] 128*40  = 5120
constexpr int S_B1 = S_W3 + HID_DIM * OUT_DIM;   // 128
constexpr int S_B2 = S_B1 + HID_DIM;             // 128
constexpr int S_T  = S_B2 + HID_DIM;             // [c][n] 128*132 = 16896
constexpr int S_H  = S_T + HID_DIM * ASTRIDE;    // [c][n] 128*132 = 16896
constexpr int S_A  = S_H;                        // alias (64*132 <= H)
constexpr int S_TOTAL = S_H + HID_DIM * ASTRIDE; // 55552 floats
constexpr int SMEM_BYTES = S_TOTAL * 4;          // 222208 B

__global__ void __launch_bounds__(512, 1)
k_mlp(const float* __restrict__ W1, const float* __restrict__ b1,
      const float* __restrict__ W2, const float* __restrict__ b2,
      const float* __restrict__ W3) {
    extern __shared__ float sm[];
    int tid = threadIdx.x;
    int lane = tid & 31;
    int wrp  = tid >> 5;               // 0..15

    for (int i = tid; i < HID_DIM * HID_DIM; i += 512) sm[S_W2 + i] = W2[i];
    for (int i = tid; i < HID_DIM * OUT_DIM; i += 512) sm[S_W3 + i] = W3[i];
    if (tid < HID_DIM) { sm[S_B1 + tid] = b1[tid]; sm[S_B2 + tid] = b2[tid]; }

    const int nb = wrp * 8;            // node base, warp-uniform (0..120)
    // proj mapping: group = tid>>6 (warp-uniform), col = tid&63 (<40 active)
    const int pg   = tid >> 6;         // 0..7
    const int pc   = tid & 63;
    const int pnb  = pg * 16;
    const bool pact = pc < OUT_DIM;

    // stage tile 0 into A (transposed [k][n])
    int g = blockIdx.x;
    for (int it = tid; it < 2048; it += 512) {
        int n = it >> 4, k4 = (it & 15) * 4;
        int node = g * TILE + n;
        float4 v = (node < N_NODES)
            ? *reinterpret_cast<const float4*>(g_agg1 + (size_t)node * IN_DIM + k4)
            : make_float4(0.f, 0.f, 0.f, 0.f);
        sm[S_A + (k4 + 0) * ASTRIDE + n] = v.x;
        sm[S_A + (k4 + 1) * ASTRIDE + n] = v.y;
        sm[S_A + (k4 + 2) * ASTRIDE + n] = v.z;
        sm[S_A + (k4 + 3) * ASTRIDE + n] = v.w;
    }

    for (; g < NTILES; g += gridDim.x) {
        int base = g * TILE;
        __syncthreads();                       // A + weights ready

        // ---- layer 1: 64 -> 128, relu. 4 cols x 8 nodes per thread. ------
        // Weights via coalesced __ldg (L1-resident after first tile).
        {
            ull acc[4][4];
            #pragma unroll
            for (int j = 0; j < 4; j++) {
                float bv = sm[S_B1 + lane + 32 * j];
                ull b = f2pack(bv, bv);
                acc[j][0] = b; acc[j][1] = b; acc[j][2] = b; acc[j][3] = b;
            }
            for (int k = 0; k < IN_DIM; k += 2) {
                #pragma unroll
                for (int kk = 0; kk < 2; kk++) {
                    const float* wr = W1 + (k + kk) * HID_DIM + lane;
                    float w0 = __ldg(wr), w1 = __ldg(wr + 32),
                          w2 = __ldg(wr + 64), w3 = __ldg(wr + 96);
                    ulonglong2 p0 = *reinterpret_cast<const ulonglong2*>(
                        &sm[S_A + (k + kk) * ASTRIDE + nb]);
                    ulonglong2 p1 = *reinterpret_cast<const ulonglong2*>(
                        &sm[S_A + (k + kk) * ASTRIDE + nb + 4]);
                    ull wp;
                    wp = f2pack(w0, w0);
                    acc[0][0] = fma2(wp, p0.x, acc[0][0]); acc[0][1] = fma2(wp, p0.y, acc[0][1]);
                    acc[0][2] = fma2(wp, p1.x, acc[0][2]); acc[0][3] = fma2(wp, p1.y, acc[0][3]);
                    wp = f2pack(w1, w1);
                    acc[1][0] = fma2(wp, p0.x, acc[1][0]); acc[1][1] = fma2(wp, p0.y, acc[1][1]);
                    acc[1][2] = fma2(wp, p1.x, acc[1][2]); acc[1][3] = fma2(wp, p1.y, acc[1][3]);
                    wp = f2pack(w2, w2);
                    acc[2][0] = fma2(wp, p0.x, acc[2][0]); acc[2][1] = fma2(wp, p0.y, acc[2][1]);
                    acc[2][2] = fma2(wp, p1.x, acc[2][2]); acc[2][3] = fma2(wp, p1.y, acc[2][3]);
                    wp = f2pack(w3, w3);
                    acc[3][0] = fma2(wp, p0.x, acc[3][0]); acc[3][1] = fma2(wp, p0.y, acc[3][1]);
                    acc[3][2] = fma2(wp, p1.x, acc[3][2]); acc[3][3] = fma2(wp, p1.y, acc[3][3]);
                }
            }
            #pragma unroll
            for (int j = 0; j < 4; j++) {
                int c = lane + 32 * j;
                float t0,t1,t2,t3,t4,t5,t6,t7;
                f2unpack(acc[j][0],t0,t1); f2unpack(acc[j][1],t2,t3);
                f2unpack(acc[j][2],t4,t5); f2unpack(acc[j][3],t6,t7);
                *reinterpret_cast<float4*>(&sm[S_T + c * ASTRIDE + nb]) =
                    make_float4(fmaxf(t0,0.f), fmaxf(t1,0.f), fmaxf(t2,0.f), fmaxf(t3,0.f));
                *reinterpret_cast<float4*>(&sm[S_T + c * ASTRIDE + nb + 4]) =
                    make_float4(fmaxf(t4,0.f), fmaxf(t5,0.f), fmaxf(t6,0.f), fmaxf(t7,0.f));
            }
        }
        __syncthreads();                       // T ready (A dead)

        // ---- layer 2: 128 -> 128, relu; writes H (clobbers A) ------------
        {
            ull acc[4][4];
            #pragma unroll
            for (int j = 0; j < 4; j++) {
                float bv = sm[S_B2 + lane + 32 * j];
                ull b = f2pack(bv, bv);
                acc[j][0] = b; acc[j][1] = b; acc[j][2] = b; acc[j][3] = b;
            }
            for (int k = 0; k < HID_DIM; k += 2) {
                #pragma unroll
                for (int kk = 0; kk < 2; kk++) {
                    const float* wr = &sm[S_W2 + (k + kk) * HID_DIM + lane];
                    float w0 = wr[0], w1 = wr[32], w2 = wr[64], w3 = wr[96];
                    ulonglong2 p0 = *reinterpret_cast<const ulonglong2*>(
                        &sm[S_T + (k + kk) * ASTRIDE + nb]);
                    ulonglong2 p1 = *reinterpret_cast<const ulonglong2*>(
                        &sm[S_T + (k + kk) * ASTRIDE + nb + 4]);
                    ull wp;
                    wp = f2pack(w0, w0);
                    acc[0][0] = fma2(wp, p0.x, acc[0][0]); acc[0][1] = fma2(wp, p0.y, acc[0][1]);
                    acc[0][2] = fma2(wp, p1.x, acc[0][2]); acc[0][3] = fma2(wp, p1.y, acc[0][3]);
                    wp = f2pack(w1, w1);
                    acc[1][0] = fma2(wp, p0.x, acc[1][0]); acc[1][1] = fma2(wp, p0.y, acc[1][1]);
                    acc[1][2] = fma2(wp, p1.x, acc[1][2]); acc[1][3] = fma2(wp, p1.y, acc[1][3]);
                    wp = f2pack(w2, w2);
                    acc[2][0] = fma2(wp, p0.x, acc[2][0]); acc[2][1] = fma2(wp, p0.y, acc[2][1]);
                    acc[2][2] = fma2(wp, p1.x, acc[2][2]); acc[2][3] = fma2(wp, p1.y, acc[2][3]);
                    wp = f2pack(w3, w3);
                    acc[3][0] = fma2(wp, p0.x, acc[3][0]); acc[3][1] = fma2(wp, p0.y, acc[3][1]);
                    acc[3][2] = fma2(wp, p1.x, acc[3][2]); acc[3][3] = fma2(wp, p1.y, acc[3][3]);
                }
            }
            #pragma unroll
            for (int j = 0; j < 4; j++) {
                int c = lane + 32 * j;
                float t0,t1,t2,t3,t4,t5,t6,t7;
                f2unpack(acc[j][0],t0,t1); f2unpack(acc[j][1],t2,t3);
                f2unpack(acc[j][2],t4,t5); f2unpack(acc[j][3],t6,t7);
                *reinterpret_cast<float4*>(&sm[S_H + c * ASTRIDE + nb]) =
                    make_float4(fmaxf(t0,0.f), fmaxf(t1,0.f), fmaxf(t2,0.f), fmaxf(t3,0.f));
                *reinterpret_cast<float4*>(&sm[S_H + c * ASTRIDE + nb + 4]) =
                    make_float4(fmaxf(t4,0.f), fmaxf(t5,0.f), fmaxf(t6,0.f), fmaxf(t7,0.f));
            }
        }
        __syncthreads();                       // H ready

        // ---- projection: 1 col x 16 nodes per thread (320 active) --------
        if (pact) {
            ull q[8];
            #pragma unroll
            for (int i = 0; i < 8; i++) q[i] = f2pack(0.f, 0.f);
            for (int k = 0; k < HID_DIM; k++) {
                float w = sm[S_W3 + k * OUT_DIM + pc];
                ull wp = f2pack(w, w);
                const float* hr = &sm[S_H + k * ASTRIDE + pnb];
                ulonglong2 p0 = *reinterpret_cast<const ulonglong2*>(hr);
                ulonglong2 p1 = *reinterpret_cast<const ulonglong2*>(hr + 4);
                ulonglong2 p2 = *reinterpret_cast<const ulonglong2*>(hr + 8);
                ulonglong2 p3 = *reinterpret_cast<const ulonglong2*>(hr + 12);
                q[0] = fma2(wp, p0.x, q[0]); q[1] = fma2(wp, p0.y, q[1]);
                q[2] = fma2(wp, p1.x, q[2]); q[3] = fma2(wp, p1.y, q[3]);
                q[4] = fma2(wp, p2.x, q[4]); q[5] = fma2(wp, p2.y, q[5]);
                q[6] = fma2(wp, p3.x, q[6]); q[7] = fma2(wp, p3.y, q[7]);
            }
            int n0 = base + pnb;
            #pragma unroll
            for (int i = 0; i < 8; i++) {
                float lo, hi;
                f2unpack(q[i], lo, hi);
                int na = n0 + 2 * i, nbx = n0 + 2 * i + 1;
                if (na < N_NODES)  g_t[(size_t)na  * OUT_DIM + pc] = lo;
                if (nbx < N_NODES) g_t[(size_t)nbx * OUT_DIM + pc] = hi;
            }
        }
        __syncthreads();                       // proj done before A clobbers H

        // ---- stage next tile into A -------------------------------------
        int gn = g + gridDim.x;
        if (gn < NTILES) {
            for (int it = tid; it < 2048; it += 512) {
                int n = it >> 4, k4 = (it & 15) * 4;
                int node = gn * TILE + n;
                float4 v = (node < N_NODES)
                    ? *reinterpret_cast<const float4*>(g_agg1 + (size_t)node * IN_DIM + k4)
                    : make_float4(0.f, 0.f, 0.f, 0.f);
                sm[S_A + (k4 + 0) * ASTRIDE + n] = v.x;
                sm[S_A + (k4 + 1) * ASTRIDE + n] = v.y;
                sm[S_A + (k4 + 2) * ASTRIDE + n] = v.z;
                sm[S_A + (k4 + 3) * ASTRIDE + n] = v.w;
            }
        }
    }
}

// ---------------- K-final2: gather2 + bias + relu + log_softmax -------------
__global__ void k_final2(const float* __restrict__ b3, float* __restrict__ out) {
    int w = (blockIdx.x * blockDim.x + threadIdx.x) >> 5;
    if (w >= N_NODES) return;
    int lane = threadIdx.x & 31;
    int p = lane / 10;
    int c = lane - p * 10;
    bool active = p < 3;
    int deg = min(g_deg[w], CAP);
    const int* row = g_csr + (size_t)w * CAP;

    float4 acc = make_float4(0.f, 0.f, 0.f, 0.f);
    if (p == 0)
        acc = *reinterpret_cast<const float4*>(g_t + (size_t)w * OUT_DIM + c * 4);

    #pragma unroll 3
    for (int j = 0; j < deg; j += 3) {
        if (active && j + p < deg) {
            int s = row[j + p];
            float4 v = *reinterpret_cast<const float4*>(
                g_t + (size_t)s * OUT_DIM + c * 4);
            acc.x += v.x; acc.y += v.y; acc.z += v.z; acc.w += v.w;
        }
    }

    float4 u;
    u.x = acc.x + __shfl_sync(0xffffffffu, acc.x, lane + 10)
                + __shfl_sync(0xffffffffu, acc.x, lane + 20);
    u.y = acc.y + __shfl_sync(0xffffffffu, acc.y, lane + 10)
                + __shfl_sync(0xffffffffu, acc.y, lane + 20);
    u.z = acc.z + __shfl_sync(0xffffffffu, acc.z, lane + 10)
                + __shfl_sync(0xffffffffu, acc.z, lane + 20);
    u.w = acc.w + __shfl_sync(0xffffffffu, acc.w, lane + 10)
                + __shfl_sync(0xffffffffu, acc.w, lane + 20);

    bool owner = lane < 10;
    float4 a = make_float4(-3.4e38f, -3.4e38f, -3.4e38f, -3.4e38f);
    if (owner) {
        float4 bv = *reinterpret_cast<const float4*>(b3 + c * 4);
        a.x = fmaxf(u.x + bv.x, 0.f);
        a.y = fmaxf(u.y + bv.y, 0.f);
        a.z = fmaxf(u.z + bv.z, 0.f);
        a.w = fmaxf(u.w + bv.w, 0.f);
    }

    float m = fmaxf(fmaxf(a.x, a.y), fmaxf(a.z, a.w));
    #pragma unroll
    for (int o = 16; o > 0; o >>= 1)
        m = fmaxf(m, __shfl_xor_sync(0xffffffffu, m, o));

    float s = owner ? (expf(a.x - m) + expf(a.y - m) +
                       expf(a.z - m) + expf(a.w - m)) : 0.f;
    #pragma unroll
    for (int o = 16; o > 0; o >>= 1)
        s += __shfl_xor_sync(0xffffffffu, s, o);

    float lse = m + logf(s);
    if (owner) {
        float4 r = make_float4(a.x - lse, a.y - lse, a.z - lse, a.w - lse);
        *reinterpret_cast<float4*>(out + (size_t)w * OUT_DIM + c * 4) = r;
    }
}

// ---------------- launch ----------------
extern "C" void kernel_launch(void* const* d_in, const int* in_sizes, int n_in,
                              void* d_out, int out_size) {
    const float* x  = (const float*)d_in[0];
    const void*  ei = d_in[1];
    const float* W1 = (const float*)d_in[2];
    const float* b1 = (const float*)d_in[3];
    const float* W2 = (const float*)d_in[4];
    const float* b2 = (const float*)d_in[5];
    const float* W3 = (const float*)d_in[6];
    const float* b3 = (const float*)d_in[7];
    float* out = (float*)d_out;

    static bool attr_set = false;
    if (!attr_set) {
        cudaFuncSetAttribute(k_mlp, cudaFuncAttributeMaxDynamicSharedMemorySize,
                             SMEM_BYTES);
        attr_set = true;
    }

    k_prep<<<(N_NODES + 255) / 256, 256>>>((const long long*)ei);
    k_build<<<(N_EDGES + 255) / 256, 256>>>(ei);
    k_gather1<<<(N_NODES * 32 + 255) / 256, 256>>>(x);
    k_mlp<<<148, 512, SMEM_BYTES>>>(W1, b1, W2, b2, W3);
    k_final2<<<(N_NODES * 32 + 255) / 256, 256>>>(b3, out);
}